// round 5
// baseline (speedup 1.0000x reference)
#include <cuda_runtime.h>

#define NB 8
#define PP 2304
#define QTOT (NB*PP)       // 18432
#define CIN 64
#define OUTC 384
#define NSTRIDE (OUTC*PP)
#define SLICE (64*PP)
#define NS 9               // split-K factor for visual attention
#define COLW 56            // smem row width: 4 pos-groups of (2 pad + 8 frames + 2 spare)
// column for (pos,n): 8 + pos*12 + n ; col-1, col-2 land in zeroed pad columns for n<2

// Scratch (allocation-free rule: __device__ globals)
__device__ float g_q[NB*8*PP];
__device__ float g_k[NB*8*PP];
__device__ float g_v[NB*32*PP];
__device__ float g_pl[NS*QTOT];
__device__ float g_pv[NS*32*QTOT];
__device__ float g_x[QTOT*64];     // [p][n][c] mega-kernel input

typedef unsigned long long u64;

__device__ __forceinline__ u64 fma2(u64 a,u64 b,u64 c){u64 d;asm("fma.rn.f32x2 %0,%1,%2,%3;":"=l"(d):"l"(a),"l"(b),"l"(c));return d;}
__device__ __forceinline__ u64 add2(u64 a,u64 b){u64 d;asm("add.rn.f32x2 %0,%1,%2;":"=l"(d):"l"(a),"l"(b));return d;}
__device__ __forceinline__ u64 pack2(float lo,float hi){u64 d;asm("mov.b64 %0,{%1,%2};":"=l"(d):"f"(lo),"f"(hi));return d;}
__device__ __forceinline__ void unpack2(u64 v,float&lo,float&hi){asm("mov.b64 {%0,%1},%2;":"=f"(lo),"=f"(hi):"l"(v));}

// ---------------------------------------------------------------------------
// Stage-0 QKV, 4-way split: block = 4 positions x 8 frames, 4 threads/cell.
// Warp wq computes outputs [wq*12, wq*12+12) for its lane's cell.
// ---------------------------------------------------------------------------
__global__ __launch_bounds__(128) void qkv0_kernel(
    const float* __restrict__ src,
    const float* __restrict__ qw, const float* __restrict__ qb,
    const float* __restrict__ kw, const float* __restrict__ kb,
    const float* __restrict__ vw, const float* __restrict__ vb)
{
    __shared__ alignas(16) float swt[64*52];   // [c][o], row pad 52 (16B-mult)
    __shared__ alignas(16) float sbs[48];
    __shared__ alignas(16) float xsm[64*COLW];

    const int tid = threadIdx.x;
    const int wq = tid >> 5, l = tid & 31;
    const int pos = l & 3, n = l >> 2;
    const int col = 8 + pos*12 + n;
    const int pg = blockIdx.x*4;

    // weights: coalesced LDG, scatter STS into [c][o]
    for (int i = tid; i < 48*64; i += 128) {
        int o = i >> 6, c = i & 63;
        float wv = (o<8) ? qw[o*64+c] : (o<16) ? kw[(o-8)*64+c] : vw[(o-16)*64+c];
        swt[c*52 + o] = wv;
    }
    if (tid < 48) sbs[tid] = (tid<8)? qb[tid] : (tid<16? kb[tid-8] : vb[tid-16]);
    // x tile: [c][cell] -> xsm
    for (int i = tid; i < 64*32; i += 128) {
        int c = i >> 5, ce = i & 31;
        int pp_ = ce & 3, nn = ce >> 2;
        xsm[c*COLW + (8 + pp_*12 + nn)] = src[(long)nn*CIN*PP + (long)c*PP + pg + pp_];
    }
    __syncthreads();

    u64 acc[6];
    {
        const u64* bp = (const u64*)sbs;
        #pragma unroll
        for (int t=0;t<6;t++) acc[t] = bp[wq*6 + t];
    }
    #pragma unroll 8
    for (int c=0;c<64;c++) {
        float xv = xsm[c*COLW + col];
        u64 x2 = pack2(xv,xv);
        const ulonglong2* wr = (const ulonglong2*)(swt + c*52 + wq*12);
        ulonglong2 w0 = wr[0], w1 = wr[1], w2 = wr[2];
        acc[0]=fma2(x2,w0.x,acc[0]); acc[1]=fma2(x2,w0.y,acc[1]);
        acc[2]=fma2(x2,w1.x,acc[2]); acc[3]=fma2(x2,w1.y,acc[3]);
        acc[4]=fma2(x2,w2.x,acc[4]); acc[5]=fma2(x2,w2.y,acc[5]);
    }
    float o12[12];
    #pragma unroll
    for (int t=0;t<6;t++) unpack2(acc[t], o12[2*t], o12[2*t+1]);
    const int p = pg + pos;
    #pragma unroll
    for (int t=0;t<12;t++) {
        int o = wq*12 + t;
        if (o < 8)       g_q[(n*8  + o     )*PP + p] = o12[t];
        else if (o < 16) g_k[(n*8  + (o-8) )*PP + p] = o12[t];
        else             g_v[(n*32 + (o-16))*PP + p] = fmaxf(o12[t], 0.f);
    }
}

// ---------------------------------------------------------------------------
// Visual attention, split-K: 48 query-tiles (384 q each, 3 q/thread) x 9 splits.
// One-pass softmax (logits O(1); shift-invariant); partials to g_pl/g_pv.
// ---------------------------------------------------------------------------
__global__ __launch_bounds__(128) void vis_attn_split(void)
{
    __shared__ alignas(16) u64 ksu[4*128];    // [c2][j]
    __shared__ alignas(16) u64 vsu[16*128];   // [c2][j]
    const int tid = threadIdx.x;
    const int tile = blockIdx.x / NS, split = blockIdx.x % NS;
    const int n = tile / 6, tw = tile % 6;
    const int qp = tw*384 + tid;
    const float* qb_ = g_q + n*8*PP;
    const float* kb_ = g_k + n*8*PP;
    const float* vb_ = g_v + n*32*PP;

    u64 qr[3][4];
    #pragma unroll
    for (int i=0;i<3;i++)
        #pragma unroll
        for (int r=0;r<4;r++)
            qr[i][r] = pack2(qb_[(2*r)*PP + qp + i*128], qb_[(2*r+1)*PP + qp + i*128]);

    float l[3] = {0.f, 0.f, 0.f};
    u64 vacc[3][16];
    #pragma unroll
    for (int i=0;i<3;i++)
        #pragma unroll
        for (int t=0;t<16;t++) vacc[i][t] = 0ULL;

    const u64 z = 0ULL;
    for (int ch = split*2; ch < split*2 + 2; ch++) {
        __syncthreads();
        const int base = ch*128 + tid;
        #pragma unroll
        for (int r=0;r<4;r++)  ksu[r*128+tid] = pack2(kb_[(2*r)*PP+base], kb_[(2*r+1)*PP+base]);
        #pragma unroll
        for (int t=0;t<16;t++) vsu[t*128+tid] = pack2(vb_[(2*t)*PP+base], vb_[(2*t+1)*PP+base]);
        __syncthreads();
        #pragma unroll 2
        for (int j=0;j<128;j++) {
            u64 k0 = ksu[j], k1 = ksu[128+j], k2 = ksu[256+j], k3 = ksu[384+j];
            float pr[3];
            #pragma unroll
            for (int i=0;i<3;i++) {
                u64 d = add2(fma2(qr[i][0],k0,fma2(qr[i][1],k1,z)),
                             fma2(qr[i][2],k2,fma2(qr[i][3],k3,z)));
                float lo,hi; unpack2(d,lo,hi);
                pr[i] = __expf(lo + hi);
                l[i] += pr[i];
            }
            u64 p0 = pack2(pr[0],pr[0]), p1 = pack2(pr[1],pr[1]), p2 = pack2(pr[2],pr[2]);
            #pragma unroll
            for (int t=0;t<16;t++) {
                u64 vr = vsu[t*128+j];
                vacc[0][t] = fma2(p0, vr, vacc[0][t]);
                vacc[1][t] = fma2(p1, vr, vacc[1][t]);
                vacc[2][t] = fma2(p2, vr, vacc[2][t]);
            }
        }
    }
    #pragma unroll
    for (int i=0;i<3;i++) {
        int q = n*PP + qp + i*128;
        g_pl[split*QTOT + q] = l[i];
        #pragma unroll
        for (int t=0;t<16;t++) {
            float lo,hi; unpack2(vacc[i][t], lo, hi);
            g_pv[(split*32 + 2*t  )*QTOT + q] = lo;
            g_pv[(split*32 + 2*t+1)*QTOT + q] = hi;
        }
    }
}

// ---------------------------------------------------------------------------
// Combine split-K partials + out-conv(32->32) + concat write to slice 0,
// plus write [oc, v] into g_x[p][n][c] for the mega temporal kernel.
// ---------------------------------------------------------------------------
__global__ __launch_bounds__(128) void combine_kernel(
    const float* __restrict__ cw, const float* __restrict__ cb,
    float* __restrict__ out)
{
    __shared__ alignas(16) u64 cwt[32*16];    // [c][o2]
    __shared__ alignas(16) float cbs[32];
    const int tid = threadIdx.x;
    for (int i = tid; i < 32*16; i += 128) {
        int c = i/16, t = i%16;
        cwt[i] = pack2(cw[(2*t)*32+c], cw[(2*t+1)*32+c]);
    }
    if (tid < 32) cbs[tid] = cb[tid];
    __syncthreads();

    const int gid = blockIdx.x*128 + tid;
    const int n = gid/PP, p = gid%PP;

    float l = 0.f;
    #pragma unroll
    for (int sp=0; sp<NS; sp++) l += g_pl[sp*QTOT + gid];
    float va[32];
    #pragma unroll
    for (int c=0;c<32;c++) va[c] = 0.f;
    for (int sp=0; sp<NS; sp++) {
        #pragma unroll
        for (int c=0;c<32;c++) va[c] += g_pv[(sp*32+c)*QTOT + gid];
    }
    float inv = 1.f / l;
    #pragma unroll
    for (int c=0;c<32;c++) va[c] *= inv;

    u64 acc[16];
    #pragma unroll
    for (int t=0;t<16;t++) acc[t] = pack2(cbs[2*t], cbs[2*t+1]);
    #pragma unroll
    for (int c=0;c<32;c++) {
        u64 x2 = pack2(va[c], va[c]);
        const ulonglong2* w2 = (const ulonglong2*)(cwt + c*16);
        #pragma unroll
        for (int t=0;t<8;t++){ ulonglong2 w = w2[t];
            acc[2*t] = fma2(x2,w.x,acc[2*t]); acc[2*t+1] = fma2(x2,w.y,acc[2*t+1]); }
    }
    float buf[64];
    #pragma unroll
    for (int t=0;t<16;t++) unpack2(acc[t], buf[2*t], buf[2*t+1]);
    #pragma unroll
    for (int c=0;c<32;c++) buf[32+c] = g_v[(n*32+c)*PP+p];

    float* ob = out + (long)n*NSTRIDE + p;   // slice 0
    #pragma unroll
    for (int o=0;o<32;o++) ob[o*PP] = buf[o];
    #pragma unroll
    for (int c=0;c<32;c++) ob[(32+c)*PP] = buf[32+c];

    float4* xp = (float4*)(g_x + ((long)p*8 + n)*64);
    #pragma unroll
    for (int t=0;t<16;t++) xp[t] = make_float4(buf[4*t],buf[4*t+1],buf[4*t+2],buf[4*t+3]);
}

// ---------------------------------------------------------------------------
// MEGA temporal: all 5 heads, 4 threads per (n,p) cell.
// Block = 4 positions x 8 frames = 32 cells, 128 threads.
// Zero-padded smem columns implement precede()'s zero frames exactly.
// Attended-v buffer ALIASES xsm rows 0..31 (xsm dead between phase 1 and the
// phase-3 rewrite; extra sync separates av reads from the xsm overwrite).
// Static smem total = 43,712 B < 48 KB limit.
// ---------------------------------------------------------------------------
__global__ __launch_bounds__(128) void mega_temporal(
    const float* __restrict__ tq_w, const float* __restrict__ tq_b,
    const float* __restrict__ tk_w, const float* __restrict__ tk_b,
    const float* __restrict__ tv_w, const float* __restrict__ tv_b,
    const float* __restrict__ tc_w, const float* __restrict__ tc_b,
    float* __restrict__ out)
{
    __shared__ alignas(16) float swt[64*52];      // qkv weights [c][o]
    __shared__ alignas(16) float cwt[32*36];      // conv weights [c][o]
    __shared__ alignas(16) float sbs[48];
    __shared__ alignas(16) float cbs[32];
    __shared__ alignas(16) float xsm[64*COLW];    // head input [c][col]; rows 0..31 reused as av buffer
    __shared__ alignas(16) float qkvsm[48*COLW];  // q/k/v      [o][col] (pads zero)
    __shared__ alignas(16) float sfa[3*32];       // softmax weights per cell

    const int tid = threadIdx.x;
    const int wq = tid >> 5, l = tid & 31;
    const int pos = l & 3, n = l >> 2;
    const int col = 8 + pos*12 + n;
    const int pg  = blockIdx.x*4;

    // zero qkvsm (establishes the zero pad columns for k and v rows)
    for (int i = tid; i < 48*COLW; i += 128) qkvsm[i] = 0.f;
    // load head-0 input from g_x
    for (int i = tid; i < 512; i += 128) {   // 512 float4
        int ce = i & 31, c4 = (i >> 5) * 4;
        int pp_ = ce & 3, nn = ce >> 2;
        float4 v4 = *(const float4*)(g_x + ((long)(pg+pp_)*8 + nn)*64 + c4);
        int cl = 8 + pp_*12 + nn;
        xsm[(c4+0)*COLW+cl]=v4.x; xsm[(c4+1)*COLW+cl]=v4.y;
        xsm[(c4+2)*COLW+cl]=v4.z; xsm[(c4+3)*COLW+cl]=v4.w;
    }
    __syncthreads();

    for (int h=0; h<5; h++) {
        // ---- weights for head h (coalesced LDG -> scatter STS)
        for (int i = tid; i < 48*64; i += 128) {
            int o = i >> 6, c = i & 63;
            float wv = (o<8)  ? tq_w[h*512  + o*64 + c]
                     : (o<16) ? tk_w[h*512  + (o-8)*64 + c]
                              : tv_w[h*2048 + (o-16)*64 + c];
            swt[c*52 + o] = wv;
        }
        for (int i = tid; i < 32*32; i += 128) {
            int o = i >> 5, c = i & 31;
            cwt[c*36 + o] = tc_w[h*1024 + o*32 + c];
        }
        if (tid < 48) sbs[tid] = (tid<8)? tq_b[h*8+tid] : (tid<16? tk_b[h*8+tid-8] : tv_b[h*32+tid-16]);
        if (tid < 32) cbs[tid] = tc_b[h*32+tid];
        __syncthreads();

        // ---- phase 1: qkv 64 -> 48 (warp wq: 12 outputs per cell)
        u64 acc[6];
        {
            const u64* bp = (const u64*)sbs;
            #pragma unroll
            for (int t=0;t<6;t++) acc[t] = bp[wq*6 + t];
        }
        #pragma unroll 8
        for (int c=0;c<64;c++) {
            float xv = xsm[c*COLW + col];
            u64 x2 = pack2(xv,xv);
            const ulonglong2* wr = (const ulonglong2*)(swt + c*52 + wq*12);
            ulonglong2 w0 = wr[0], w1 = wr[1], w2 = wr[2];
            acc[0]=fma2(x2,w0.x,acc[0]); acc[1]=fma2(x2,w0.y,acc[1]);
            acc[2]=fma2(x2,w1.x,acc[2]); acc[3]=fma2(x2,w1.y,acc[3]);
            acc[4]=fma2(x2,w2.x,acc[4]); acc[5]=fma2(x2,w2.y,acc[5]);
        }
        {
            float o12[12];
            #pragma unroll
            for (int t=0;t<6;t++) unpack2(acc[t], o12[2*t], o12[2*t+1]);
            #pragma unroll
            for (int t=0;t<12;t++) {
                int o = wq*12 + t;
                float vv = (o >= 16) ? fmaxf(o12[t], 0.f) : o12[t];
                qkvsm[o*COLW + col] = vv;
            }
        }
        __syncthreads();   // qkv ready; xsm now dead (safe to reuse rows 0..31)

        // ---- phase 2a: per-cell 3-frame softmax (warp 0 only)
        if (tid < 32) {
            int c2 = 8 + (tid & 3)*12 + (tid >> 2);
            float l2=0.f, l1=0.f, l0=0.f;
            #pragma unroll
            for (int c=0;c<8;c++) {
                float q = qkvsm[c*COLW + c2];
                l2 += q * qkvsm[(8+c)*COLW + c2];
                l1 += q * qkvsm[(8+c)*COLW + c2 - 1];   // zero col for n<1
                l0 += q * qkvsm[(8+c)*COLW + c2 - 2];   // zero col for n<2
            }
            float m  = fmaxf(l0, fmaxf(l1, l2));
            float e0 = __expf(l0-m), e1 = __expf(l1-m), e2 = __expf(l2-m);
            float inv = 1.f/(e0+e1+e2);
            sfa[tid]      = e0*inv;   // weight for frame t-2
            sfa[32+tid]   = e1*inv;   // t-1
            sfa[64+tid]   = e2*inv;   // t
        }
        __syncthreads();

        // ---- phase 2b: attended v into xsm rows 0..31 (warp wq: 8 channels/cell)
        {
            float a0 = sfa[l], a1 = sfa[32+l], a2 = sfa[64+l];
            #pragma unroll
            for (int j=0;j<8;j++) {
                int c = wq*8 + j;
                float v0 = qkvsm[(16+c)*COLW + col];
                float v1 = qkvsm[(16+c)*COLW + col - 1];  // zero for n<1
                float v2 = qkvsm[(16+c)*COLW + col - 2];  // zero for n<2
                xsm[c*COLW + col] = a2*v0 + a1*v1 + a0*v2;
            }
        }
        __syncthreads();

        // ---- phase 3: out-conv 32->32 (warp wq: 8 outputs) into regs
        u64 ca[4];
        {
            const u64* bp = (const u64*)cbs;
            #pragma unroll
            for (int t=0;t<4;t++) ca[t] = bp[wq*4 + t];
        }
        #pragma unroll 8
        for (int c=0;c<32;c++) {
            float av = xsm[c*COLW + col];
            u64 x2 = pack2(av,av);
            const ulonglong2* wr = (const ulonglong2*)(cwt + c*36 + wq*8);
            ulonglong2 w0 = wr[0], w1 = wr[1];
            ca[0]=fma2(x2,w0.x,ca[0]); ca[1]=fma2(x2,w0.y,ca[1]);
            ca[2]=fma2(x2,w1.x,ca[2]); ca[3]=fma2(x2,w1.y,ca[3]);
        }
        __syncthreads();   // all av reads done before xsm overwrite

        {
            float oc[8];
            #pragma unroll
            for (int t=0;t<4;t++) unpack2(ca[t], oc[2*t], oc[2*t+1]);
            float* ob = out + (long)n*NSTRIDE + (long)(h+1)*SLICE + pg + pos;
            #pragma unroll
            for (int j=0;j<8;j++) {
                int o = wq*8 + j;
                float vv = qkvsm[(16+o)*COLW + col];
                ob[o*PP]      = oc[j];
                ob[(32+o)*PP] = vv;
                xsm[o*COLW + col]      = oc[j];
                xsm[(32+o)*COLW + col] = vv;
            }
        }
        __syncthreads();
    }
}

// ---------------------------------------------------------------------------
extern "C" void kernel_launch(void* const* d_in, const int* in_sizes, int n_in,
                              void* d_out, int out_size)
{
    const float* x    = (const float*)d_in[0];
    const float* vq_w = (const float*)d_in[1];
    const float* vq_b = (const float*)d_in[2];
    const float* vk_w = (const float*)d_in[3];
    const float* vk_b = (const float*)d_in[4];
    const float* vv_w = (const float*)d_in[5];
    const float* vv_b = (const float*)d_in[6];
    const float* vc_w = (const float*)d_in[7];
    const float* vc_b = (const float*)d_in[8];
    const float* tq_w = (const float*)d_in[9];
    const float* tq_b = (const float*)d_in[10];
    const float* tk_w = (const float*)d_in[11];
    const float* tk_b = (const float*)d_in[12];
    const float* tv_w = (const float*)d_in[13];
    const float* tv_b = (const float*)d_in[14];
    const float* tc_w = (const float*)d_in[15];
    const float* tc_b = (const float*)d_in[16];
    float* out = (float*)d_out;

    qkv0_kernel<<<576,128>>>(x, vq_w, vq_b, vk_w, vk_b, vv_w, vv_b);
    vis_attn_split<<<48*NS,128>>>();
    combine_kernel<<<144,128>>>(vc_w, vc_b, out);
    mega_temporal<<<576,128>>>(tq_w, tq_b, tk_w, tk_b, tv_w, tv_b, tc_w, tc_b, out);
}

// round 6
// speedup vs baseline: 1.0286x; 1.0286x over previous
#include <cuda_runtime.h>

#define NB 8
#define PP 2304
#define QTOT (NB*PP)       // 18432
#define CIN 64
#define OUTC 384
#define NSTRIDE (OUTC*PP)
#define SLICE (64*PP)
#define NS 9               // split-K factor for visual attention
#define COLW 56            // (qkv0 only) smem row width
#define XROWP 68           // mega xsm row pad (floats): conflict-free .128
#define QROWP 52           // mega qkvsm row pad (floats): conflict-free .128

// Scratch (allocation-free rule: __device__ globals)
__device__ float g_q[NB*8*PP];
__device__ float g_k[NB*8*PP];
__device__ float g_v[NB*32*PP];
__device__ float g_pl[NS*QTOT];
__device__ float g_pv[NS*32*QTOT];
__device__ float g_x[QTOT*64];     // [p][n][c] mega-kernel input

typedef unsigned long long u64;

__device__ __forceinline__ u64 fma2(u64 a,u64 b,u64 c){u64 d;asm("fma.rn.f32x2 %0,%1,%2,%3;":"=l"(d):"l"(a),"l"(b),"l"(c));return d;}
__device__ __forceinline__ u64 add2(u64 a,u64 b){u64 d;asm("add.rn.f32x2 %0,%1,%2;":"=l"(d):"l"(a),"l"(b));return d;}
__device__ __forceinline__ u64 pack2(float lo,float hi){u64 d;asm("mov.b64 %0,{%1,%2};":"=l"(d):"f"(lo),"f"(hi));return d;}
__device__ __forceinline__ void unpack2(u64 v,float&lo,float&hi){asm("mov.b64 {%0,%1},%2;":"=f"(lo),"=f"(hi):"l"(v));}

// ---------------------------------------------------------------------------
// Stage-0 QKV, 4-way split (unchanged from passing version).
// ---------------------------------------------------------------------------
__global__ __launch_bounds__(128) void qkv0_kernel(
    const float* __restrict__ src,
    const float* __restrict__ qw, const float* __restrict__ qb,
    const float* __restrict__ kw, const float* __restrict__ kb,
    const float* __restrict__ vw, const float* __restrict__ vb)
{
    __shared__ alignas(16) float swt[64*52];
    __shared__ alignas(16) float sbs[48];
    __shared__ alignas(16) float xsm[64*COLW];

    const int tid = threadIdx.x;
    const int wq = tid >> 5, l = tid & 31;
    const int pos = l & 3, n = l >> 2;
    const int col = 8 + pos*12 + n;
    const int pg = blockIdx.x*4;

    for (int i = tid; i < 48*64; i += 128) {
        int o = i >> 6, c = i & 63;
        float wv = (o<8) ? qw[o*64+c] : (o<16) ? kw[(o-8)*64+c] : vw[(o-16)*64+c];
        swt[c*52 + o] = wv;
    }
    if (tid < 48) sbs[tid] = (tid<8)? qb[tid] : (tid<16? kb[tid-8] : vb[tid-16]);
    for (int i = tid; i < 64*32; i += 128) {
        int c = i >> 5, ce = i & 31;
        int pp_ = ce & 3, nn = ce >> 2;
        xsm[c*COLW + (8 + pp_*12 + nn)] = src[(long)nn*CIN*PP + (long)c*PP + pg + pp_];
    }
    __syncthreads();

    u64 acc[6];
    {
        const u64* bp = (const u64*)sbs;
        #pragma unroll
        for (int t=0;t<6;t++) acc[t] = bp[wq*6 + t];
    }
    #pragma unroll 8
    for (int c=0;c<64;c++) {
        float xv = xsm[c*COLW + col];
        u64 x2 = pack2(xv,xv);
        const ulonglong2* wr = (const ulonglong2*)(swt + c*52 + wq*12);
        ulonglong2 w0 = wr[0], w1 = wr[1], w2 = wr[2];
        acc[0]=fma2(x2,w0.x,acc[0]); acc[1]=fma2(x2,w0.y,acc[1]);
        acc[2]=fma2(x2,w1.x,acc[2]); acc[3]=fma2(x2,w1.y,acc[3]);
        acc[4]=fma2(x2,w2.x,acc[4]); acc[5]=fma2(x2,w2.y,acc[5]);
    }
    float o12[12];
    #pragma unroll
    for (int t=0;t<6;t++) unpack2(acc[t], o12[2*t], o12[2*t+1]);
    const int p = pg + pos;
    #pragma unroll
    for (int t=0;t<12;t++) {
        int o = wq*12 + t;
        if (o < 8)       g_q[(n*8  + o     )*PP + p] = o12[t];
        else if (o < 16) g_k[(n*8  + (o-8) )*PP + p] = o12[t];
        else             g_v[(n*32 + (o-16))*PP + p] = fmaxf(o12[t], 0.f);
    }
}

// ---------------------------------------------------------------------------
// Visual attention, split-K (unchanged from passing version).
// ---------------------------------------------------------------------------
__global__ __launch_bounds__(128) void vis_attn_split(void)
{
    __shared__ alignas(16) u64 ksu[4*128];
    __shared__ alignas(16) u64 vsu[16*128];
    const int tid = threadIdx.x;
    const int tile = blockIdx.x / NS, split = blockIdx.x % NS;
    const int n = tile / 6, tw = tile % 6;
    const int qp = tw*384 + tid;
    const float* qb_ = g_q + n*8*PP;
    const float* kb_ = g_k + n*8*PP;
    const float* vb_ = g_v + n*32*PP;

    u64 qr[3][4];
    #pragma unroll
    for (int i=0;i<3;i++)
        #pragma unroll
        for (int r=0;r<4;r++)
            qr[i][r] = pack2(qb_[(2*r)*PP + qp + i*128], qb_[(2*r+1)*PP + qp + i*128]);

    float l[3] = {0.f, 0.f, 0.f};
    u64 vacc[3][16];
    #pragma unroll
    for (int i=0;i<3;i++)
        #pragma unroll
        for (int t=0;t<16;t++) vacc[i][t] = 0ULL;

    const u64 z = 0ULL;
    for (int ch = split*2; ch < split*2 + 2; ch++) {
        __syncthreads();
        const int base = ch*128 + tid;
        #pragma unroll
        for (int r=0;r<4;r++)  ksu[r*128+tid] = pack2(kb_[(2*r)*PP+base], kb_[(2*r+1)*PP+base]);
        #pragma unroll
        for (int t=0;t<16;t++) vsu[t*128+tid] = pack2(vb_[(2*t)*PP+base], vb_[(2*t+1)*PP+base]);
        __syncthreads();
        #pragma unroll 2
        for (int j=0;j<128;j++) {
            u64 k0 = ksu[j], k1 = ksu[128+j], k2 = ksu[256+j], k3 = ksu[384+j];
            float pr[3];
            #pragma unroll
            for (int i=0;i<3;i++) {
                u64 d = add2(fma2(qr[i][0],k0,fma2(qr[i][1],k1,z)),
                             fma2(qr[i][2],k2,fma2(qr[i][3],k3,z)));
                float lo,hi; unpack2(d,lo,hi);
                pr[i] = __expf(lo + hi);
                l[i] += pr[i];
            }
            u64 p0 = pack2(pr[0],pr[0]), p1 = pack2(pr[1],pr[1]), p2 = pack2(pr[2],pr[2]);
            #pragma unroll
            for (int t=0;t<16;t++) {
                u64 vr = vsu[t*128+j];
                vacc[0][t] = fma2(p0, vr, vacc[0][t]);
                vacc[1][t] = fma2(p1, vr, vacc[1][t]);
                vacc[2][t] = fma2(p2, vr, vacc[2][t]);
            }
        }
    }
    #pragma unroll
    for (int i=0;i<3;i++) {
        int q = n*PP + qp + i*128;
        g_pl[split*QTOT + q] = l[i];
        #pragma unroll
        for (int t=0;t<16;t++) {
            float lo,hi; unpack2(vacc[i][t], lo, hi);
            g_pv[(split*32 + 2*t  )*QTOT + q] = lo;
            g_pv[(split*32 + 2*t+1)*QTOT + q] = hi;
        }
    }
}

// ---------------------------------------------------------------------------
// Combine split-K partials (unchanged from passing version).
// ---------------------------------------------------------------------------
__global__ __launch_bounds__(128) void combine_kernel(
    const float* __restrict__ cw, const float* __restrict__ cb,
    float* __restrict__ out)
{
    __shared__ alignas(16) u64 cwt[32*16];
    __shared__ alignas(16) float cbs[32];
    const int tid = threadIdx.x;
    for (int i = tid; i < 32*16; i += 128) {
        int c = i/16, t = i%16;
        cwt[i] = pack2(cw[(2*t)*32+c], cw[(2*t+1)*32+c]);
    }
    if (tid < 32) cbs[tid] = cb[tid];
    __syncthreads();

    const int gid = blockIdx.x*128 + tid;
    const int n = gid/PP, p = gid%PP;

    float l = 0.f;
    #pragma unroll
    for (int sp=0; sp<NS; sp++) l += g_pl[sp*QTOT + gid];
    float va[32];
    #pragma unroll
    for (int c=0;c<32;c++) va[c] = 0.f;
    for (int sp=0; sp<NS; sp++) {
        #pragma unroll
        for (int c=0;c<32;c++) va[c] += g_pv[(sp*32+c)*QTOT + gid];
    }
    float inv = 1.f / l;
    #pragma unroll
    for (int c=0;c<32;c++) va[c] *= inv;

    u64 acc[16];
    #pragma unroll
    for (int t=0;t<16;t++) acc[t] = pack2(cbs[2*t], cbs[2*t+1]);
    #pragma unroll
    for (int c=0;c<32;c++) {
        u64 x2 = pack2(va[c], va[c]);
        const ulonglong2* w2 = (const ulonglong2*)(cwt + c*16);
        #pragma unroll
        for (int t=0;t<8;t++){ ulonglong2 w = w2[t];
            acc[2*t] = fma2(x2,w.x,acc[2*t]); acc[2*t+1] = fma2(x2,w.y,acc[2*t+1]); }
    }
    float buf[64];
    #pragma unroll
    for (int t=0;t<16;t++) unpack2(acc[t], buf[2*t], buf[2*t+1]);
    #pragma unroll
    for (int c=0;c<32;c++) buf[32+c] = g_v[(n*32+c)*PP+p];

    float* ob = out + (long)n*NSTRIDE + p;
    #pragma unroll
    for (int o=0;o<32;o++) ob[o*PP] = buf[o];
    #pragma unroll
    for (int c=0;c<32;c++) ob[(32+c)*PP] = buf[32+c];

    float4* xp = (float4*)(g_x + ((long)p*8 + n)*64);
    #pragma unroll
    for (int t=0;t<16;t++) xp[t] = make_float4(buf[4*t],buf[4*t+1],buf[4*t+2],buf[4*t+3]);
}

// ---------------------------------------------------------------------------
// MEGA temporal v2: 3 barriers/head, vectorized smem, redundant per-thread
// softmax, conv fused with attention combine.
// Block = 4 positions x 8 frames = 32 cells; lane = cell; warp = output quarter.
// qkvsm rows: cellr = pos*10 + 2 + n; rows pos*10+{0,1} stay zero forever ->
// reading rows cellr-1 / cellr-2 implements precede()'s zero frames exactly.
// ---------------------------------------------------------------------------
__global__ __launch_bounds__(128) void mega_temporal(
    const float* __restrict__ tq_w, const float* __restrict__ tq_b,
    const float* __restrict__ tk_w, const float* __restrict__ tk_b,
    const float* __restrict__ tv_w, const float* __restrict__ tv_b,
    const float* __restrict__ tc_w, const float* __restrict__ tc_b,
    float* __restrict__ out)
{
    __shared__ alignas(16) float swt[64*QROWP];   // qkv weights [c][o] (52 pad)
    __shared__ alignas(16) float cwt[32*36];      // conv weights [c][o] (36 pad)
    __shared__ alignas(16) float sbs[48];
    __shared__ alignas(16) float cbs[32];
    __shared__ alignas(16) float xsm[32*XROWP];   // head input [cell][c] (68 pad)
    __shared__ alignas(16) float qkvsm[42*QROWP]; // q/k/v [cellr][o] (52 pad)

    const int tid  = threadIdx.x;
    const int wq   = tid >> 5, lane = tid & 31;
    const int pos  = lane >> 3, n = lane & 7;
    const int cell = lane;
    const int cellr = pos*10 + 2 + n;
    const int pg   = blockIdx.x*4;

    // zero qkvsm once (establishes guard rows; real rows rewritten each head)
    for (int i = tid; i < 42*QROWP; i += 128) qkvsm[i] = 0.f;

    // head-0 input: thread loads its cell's c-quarter (4x LDG.128 -> STS.128)
    {
        const float* gx = g_x + ((long)(pg+pos)*8 + n)*64 + wq*16;
        #pragma unroll
        for (int k=0;k<4;k++) {
            float4 v4 = *(const float4*)(gx + 4*k);
            *(float4*)(xsm + cell*XROWP + wq*16 + 4*k) = v4;
        }
    }

    for (int h=0; h<5; h++) {
        __syncthreads();   // barrier A: xsm writes done, prev weight reads done

        // ---- weights for head h (coalesced LDG -> scatter STS)
        for (int i = tid; i < 48*64; i += 128) {
            int o = i >> 6, c = i & 63;
            float wv = (o<8)  ? tq_w[h*512  + o*64 + c]
                     : (o<16) ? tk_w[h*512  + (o-8)*64 + c]
                              : tv_w[h*2048 + (o-16)*64 + c];
            swt[c*QROWP + o] = wv;
        }
        for (int i = tid; i < 32*32; i += 128) {
            int o = i >> 5, c = i & 31;
            cwt[c*36 + o] = tc_w[h*1024 + o*32 + c];
        }
        if (tid < 48) sbs[tid] = (tid<8)? tq_b[h*8+tid] : (tid<16? tk_b[h*8+tid-8] : tv_b[h*32+tid-16]);
        if (tid < 32) cbs[tid] = tc_b[h*32+tid];
        __syncthreads();   // barrier B: weights ready

        // ---- phase 1: qkv 64 -> 48 (warp wq: outputs [12wq, 12wq+12))
        u64 acc[6];
        {
            const u64* bp = (const u64*)sbs;
            #pragma unroll
            for (int t=0;t<6;t++) acc[t] = bp[wq*6 + t];
        }
        #pragma unroll
        for (int c4=0; c4<64; c4+=4) {
            float4 xv = *(const float4*)(xsm + cell*XROWP + c4);
            float xs[4] = {xv.x, xv.y, xv.z, xv.w};
            #pragma unroll
            for (int j=0;j<4;j++) {
                u64 x2 = pack2(xs[j], xs[j]);
                const ulonglong2* wr = (const ulonglong2*)(swt + (c4+j)*QROWP + wq*12);
                ulonglong2 w0 = wr[0], w1 = wr[1], w2 = wr[2];
                acc[0]=fma2(x2,w0.x,acc[0]); acc[1]=fma2(x2,w0.y,acc[1]);
                acc[2]=fma2(x2,w1.x,acc[2]); acc[3]=fma2(x2,w1.y,acc[3]);
                acc[4]=fma2(x2,w2.x,acc[4]); acc[5]=fma2(x2,w2.y,acc[5]);
            }
        }
        {
            float o12[12];
            #pragma unroll
            for (int t=0;t<6;t++) unpack2(acc[t], o12[2*t], o12[2*t+1]);
            #pragma unroll
            for (int t=0;t<12;t++)
                if (12*wq + t >= 16) o12[t] = fmaxf(o12[t], 0.f);   // ReLU on v
            float* qr = qkvsm + cellr*QROWP + wq*12;
            *(float4*)(qr  ) = make_float4(o12[0],o12[1],o12[2],o12[3]);
            *(float4*)(qr+4) = make_float4(o12[4],o12[5],o12[6],o12[7]);
            *(float4*)(qr+8) = make_float4(o12[8],o12[9],o12[10],o12[11]);
        }
        __syncthreads();   // barrier C: qkv ready

        // ---- softmax (every thread, own cell; guard rows give zero logits/v)
        float a0, a1, a2;
        {
            const float* qp = qkvsm + cellr*QROWP;
            float4 qa = *(const float4*)(qp),      qb2 = *(const float4*)(qp+4);
            float4 k0a = *(const float4*)(qp+8),   k0b = *(const float4*)(qp+12);
            float4 k1a = *(const float4*)(qp+8-QROWP),   k1b = *(const float4*)(qp+12-QROWP);
            float4 k2a = *(const float4*)(qp+8-2*QROWP), k2b = *(const float4*)(qp+12-2*QROWP);
            float l2 = qa.x*k0a.x + qa.y*k0a.y + qa.z*k0a.z + qa.w*k0a.w
                     + qb2.x*k0b.x + qb2.y*k0b.y + qb2.z*k0b.z + qb2.w*k0b.w;
            float l1 = qa.x*k1a.x + qa.y*k1a.y + qa.z*k1a.z + qa.w*k1a.w
                     + qb2.x*k1b.x + qb2.y*k1b.y + qb2.z*k1b.z + qb2.w*k1b.w;
            float l0 = qa.x*k2a.x + qa.y*k2a.y + qa.z*k2a.z + qa.w*k2a.w
                     + qb2.x*k2b.x + qb2.y*k2b.y + qb2.z*k2b.z + qb2.w*k2b.w;
            float m  = fmaxf(l0, fmaxf(l1, l2));
            float e0 = __expf(l0-m), e1 = __expf(l1-m), e2 = __expf(l2-m);
            float inv = 1.f/(e0+e1+e2);
            a0 = e0*inv; a1 = e1*inv; a2 = e2*inv;
        }

        // ---- fused attention-combine + out-conv (warp wq: conv outputs [8wq,8wq+8))
        u64 ca[4];
        {
            const u64* bp = (const u64*)cbs;
            #pragma unroll
            for (int t=0;t<4;t++) ca[t] = bp[wq*4 + t];
        }
        {
            const float* vr = qkvsm + cellr*QROWP + 16;
            #pragma unroll
            for (int c4=0; c4<32; c4+=4) {
                float4 v0 = *(const float4*)(vr + c4);
                float4 v1 = *(const float4*)(vr + c4 - QROWP);
                float4 v2 = *(const float4*)(vr + c4 - 2*QROWP);
                float av[4];
                av[0] = a2*v0.x + a1*v1.x + a0*v2.x;
                av[1] = a2*v0.y + a1*v1.y + a0*v2.y;
                av[2] = a2*v0.z + a1*v1.z + a0*v2.z;
                av[3] = a2*v0.w + a1*v1.w + a0*v2.w;
                #pragma unroll
                for (int j=0;j<4;j++) {
                    u64 x2 = pack2(av[j], av[j]);
                    const ulonglong2* wr = (const ulonglong2*)(cwt + (c4+j)*36 + wq*8);
                    ulonglong2 w0 = wr[0], w1 = wr[1];
                    ca[0]=fma2(x2,w0.x,ca[0]); ca[1]=fma2(x2,w0.y,ca[1]);
                    ca[2]=fma2(x2,w1.x,ca[2]); ca[3]=fma2(x2,w1.y,ca[3]);
                }
            }
        }
        {
            float oc[8];
            #pragma unroll
            for (int t=0;t<4;t++) unpack2(ca[t], oc[2*t], oc[2*t+1]);
            // own quarter of v for concat + next-x
            float4 va = *(const float4*)(qkvsm + cellr*QROWP + 16 + wq*8);
            float4 vb = *(const float4*)(qkvsm + cellr*QROWP + 16 + wq*8 + 4);
            float vq[8] = {va.x,va.y,va.z,va.w, vb.x,vb.y,vb.z,vb.w};

            float* ob = out + (long)n*NSTRIDE + (long)(h+1)*SLICE + pg + pos;
            #pragma unroll
            for (int j=0;j<8;j++) {
                ob[(8*wq+j)*PP]      = oc[j];
                ob[(32+8*wq+j)*PP]   = vq[j];
            }
            // next head input (xsm rewrite; barrier A protects readers)
            float* xr = xsm + cell*XROWP;
            *(float4*)(xr + 8*wq    ) = make_float4(oc[0],oc[1],oc[2],oc[3]);
            *(float4*)(xr + 8*wq + 4) = make_float4(oc[4],oc[5],oc[6],oc[7]);
            *(float4*)(xr + 32 + 8*wq    ) = va;
            *(float4*)(xr + 32 + 8*wq + 4) = vb;
        }
    }
}

// ---------------------------------------------------------------------------
extern "C" void kernel_launch(void* const* d_in, const int* in_sizes, int n_in,
                              void* d_out, int out_size)
{
    const float* x    = (const float*)d_in[0];
    const float* vq_w = (const float*)d_in[1];
    const float* vq_b = (const float*)d_in[2];
    const float* vk_w = (const float*)d_in[3];
    const float* vk_b = (const float*)d_in[4];
    const float* vv_w = (const float*)d_in[5];
    const float* vv_b = (const float*)d_in[6];
    const float* vc_w = (const float*)d_in[7];
    const float* vc_b = (const float*)d_in[8];
    const float* tq_w = (const float*)d_in[9];
    const float* tq_b = (const float*)d_in[10];
    const float* tk_w = (const float*)d_in[11];
    const float* tk_b = (const float*)d_in[12];
    const float* tv_w = (const float*)d_in[13];
    const float* tv_b = (const float*)d_in[14];
    const float* tc_w = (const float*)d_in[15];
    const float* tc_b = (const float*)d_in[16];
    float* out = (float*)d_out;

    qkv0_kernel<<<576,128>>>(x, vq_w, vq_b, vk_w, vk_b, vv_w, vv_b);
    vis_attn_split<<<48*NS,128>>>();
    combine_kernel<<<144,128>>>(vc_w, vc_b, out);
    mega_temporal<<<576,128>>>(tq_w, tq_b, tk_w, tk_b, tv_w, tv_b, tc_w, tc_b, out);
}